// round 11
// baseline (speedup 1.0000x reference)
#include <cuda_runtime.h>

typedef unsigned long long ull;

#define BB 32
#define LL 4096
#define HH 128
#define H2 256
#define VV 32000
#define TOK 64
#define NTOK (BB*LL)

// ---- helpers ---------------------------------------------------------------
__device__ __forceinline__ ull pk2(float lo, float hi) {
    ull r; asm("mov.b64 %0, {%1, %2};" : "=l"(r) : "f"(lo), "f"(hi)); return r;
}
__device__ __forceinline__ void upk2(ull v, float& lo, float& hi) {
    asm("mov.b64 {%0, %1}, %2;" : "=f"(lo), "=f"(hi) : "l"(v));
}
__device__ __forceinline__ ull f2fma(ull a, ull b, ull c) {
    ull d; asm("fma.rn.f32x2 %0, %1, %2, %3;" : "=l"(d) : "l"(a), "l"(b), "l"(c)); return d;
}
__device__ __forceinline__ void cpasync16(unsigned s, const void* g) {
    asm volatile("cp.async.ca.shared.global [%0], [%1], 16;" :: "r"(s), "l"(g));
}
__device__ __forceinline__ void cpcommit() { asm volatile("cp.async.commit_group;"); }
__device__ __forceinline__ void cpwait1()  { asm volatile("cp.async.wait_group 1;"); }
__device__ __forceinline__ void cpwait0()  { asm volatile("cp.async.wait_group 0;"); }

// Scratch
__device__ float g_k[(size_t)NTOK * HH];   // normalized kn, (B*L, H)
__device__ float g_nrm[NTOK];              // norm_eff
__device__ float g_read[BB * HH];
__device__ float g_r2[BB * HH];

// ---------------------------------------------------------------------------
// Kernel A v3 (R10 verbatim): fused gather -> MLP(relu) -> residual+LN ->
// k-proj. 96KB smem, 2 CTAs/SM, cp.async double-buffered weight stages.
// ---------------------------------------------------------------------------
__global__ void __launch_bounds__(256, 2) kA(
    const int* __restrict__ seq, const float* __restrict__ embed,
    const float* __restrict__ W1, const float* __restrict__ b1,
    const float* __restrict__ W2, const float* __restrict__ b2,
    const float* __restrict__ lng, const float* __restrict__ lnb,
    const float* __restrict__ Wkp)
{
    extern __shared__ float sm[];
    float* sH = sm;              // 64 x 128 (32KB)
    float* sA = sm + 8192;       // 64 x 128 (32KB)
    float* sW = sm + 16384;      // 2 x 4096 (2 x 16KB stage buffers)
    __shared__ int sSeq[TOK];
    __shared__ float sInv[TOK];

    const int tid = threadIdx.x;
    const int t0  = blockIdx.x * TOK;
    if (tid < TOK) sSeq[tid] = seq[t0 + tid];
    __syncthreads();

    // gather embeddings
    {
        float4* d = (float4*)sH;
        const float4* e = (const float4*)embed;
        for (int idx = tid; idx < TOK * (HH / 4); idx += 256) {
            int r = idx >> 5;
            d[idx] = e[(size_t)sSeq[r] * (HH / 4) + (idx & 31)];
        }
    }
    __syncthreads();

    const int tx = tid & 15, ty = tid >> 4;
    const unsigned swb = (unsigned)__cvta_generic_to_shared(sW);

    float acc2[4][8];                      // GEMM2 (F) accumulator, both halves
#pragma unroll
    for (int r = 0; r < 4; r++)
#pragma unroll
        for (int c = 0; c < 8; c++) acc2[r][c] = 0.f;

    for (int hh = 0; hh < 2; hh++) {
        // ---- GEMM1 half: A[:,hh*128..] = H @ W1[:, hh*128..]  (64x128x128)
        float acc[4][8];
#pragma unroll
        for (int r = 0; r < 4; r++)
#pragma unroll
            for (int c = 0; c < 8; c++) acc[r][c] = 0.f;

        {
            const float4* s = (const float4*)W1;   // row = 64 float4
#pragma unroll
            for (int j = 0; j < 4; j++) {
                int idx = tid + j * 256;
                cpasync16(swb + (unsigned)idx * 16,
                          s + (size_t)(idx >> 5) * 64 + hh * 32 + (idx & 31));
            }
            cpcommit();
        }
        for (int kb = 0; kb < 4; kb++) {
            if (kb < 3) {
                const float4* s = (const float4*)W1;
                unsigned dst = swb + ((kb + 1) & 1) * 16384u;
#pragma unroll
                for (int j = 0; j < 4; j++) {
                    int idx = tid + j * 256;
                    cpasync16(dst + (unsigned)idx * 16,
                              s + (size_t)((kb + 1) * 32 + (idx >> 5)) * 64 + hh * 32 + (idx & 31));
                }
                cpcommit();
                cpwait1();
            } else cpwait0();
            __syncthreads();
            const float* wb = sW + (kb & 1) * 4096;
#pragma unroll
            for (int kk = 0; kk < 32; kk++) {
                float hv[4];
#pragma unroll
                for (int r = 0; r < 4; r++) hv[r] = sH[(ty * 4 + r) * HH + kb * 32 + kk];
#pragma unroll
                for (int q = 0; q < 2; q++) {
                    float4 w = ((const float4*)wb)[kk * 32 + q * 16 + tx];
#pragma unroll
                    for (int r = 0; r < 4; r++) {
                        acc[r][q * 4 + 0] = fmaf(hv[r], w.x, acc[r][q * 4 + 0]);
                        acc[r][q * 4 + 1] = fmaf(hv[r], w.y, acc[r][q * 4 + 1]);
                        acc[r][q * 4 + 2] = fmaf(hv[r], w.z, acc[r][q * 4 + 2]);
                        acc[r][q * 4 + 3] = fmaf(hv[r], w.w, acc[r][q * 4 + 3]);
                    }
                }
            }
            __syncthreads();
        }
        // bias + relu -> sA
#pragma unroll
        for (int q = 0; q < 2; q++)
#pragma unroll
            for (int u = 0; u < 4; u++) {
                int c = q * 64 + tx * 4 + u;
                float bb = b1[hh * 128 + c];
#pragma unroll
                for (int r = 0; r < 4; r++) {
                    float v = acc[r][q * 4 + u] + bb;
                    sA[(ty * 4 + r) * HH + c] = v > 0.f ? v : 0.f;
                }
            }
        __syncthreads();

        // ---- GEMM2 half: F += A_half @ W2[hh*128.., :]  (64x128x128)
        {
            const float4* s = (const float4*)W2;   // row = 32 float4
#pragma unroll
            for (int j = 0; j < 4; j++) {
                int idx = tid + j * 256;
                cpasync16(swb + (unsigned)idx * 16,
                          s + (size_t)(hh * 128 + (idx >> 5)) * 32 + (idx & 31));
            }
            cpcommit();
        }
        for (int kb = 0; kb < 4; kb++) {
            if (kb < 3) {
                const float4* s = (const float4*)W2;
                unsigned dst = swb + ((kb + 1) & 1) * 16384u;
#pragma unroll
                for (int j = 0; j < 4; j++) {
                    int idx = tid + j * 256;
                    cpasync16(dst + (unsigned)idx * 16,
                              s + (size_t)(hh * 128 + (kb + 1) * 32 + (idx >> 5)) * 32 + (idx & 31));
                }
                cpcommit();
                cpwait1();
            } else cpwait0();
            __syncthreads();
            const float* wb = sW + (kb & 1) * 4096;
#pragma unroll
            for (int kk = 0; kk < 32; kk++) {
                float av[4];
#pragma unroll
                for (int r = 0; r < 4; r++) av[r] = sA[(ty * 4 + r) * HH + kb * 32 + kk];
#pragma unroll
                for (int q = 0; q < 2; q++) {
                    float4 w = ((const float4*)wb)[kk * 32 + q * 16 + tx];
#pragma unroll
                    for (int r = 0; r < 4; r++) {
                        acc2[r][q * 4 + 0] = fmaf(av[r], w.x, acc2[r][q * 4 + 0]);
                        acc2[r][q * 4 + 1] = fmaf(av[r], w.y, acc2[r][q * 4 + 1]);
                        acc2[r][q * 4 + 2] = fmaf(av[r], w.z, acc2[r][q * 4 + 2]);
                        acc2[r][q * 4 + 3] = fmaf(av[r], w.w, acc2[r][q * 4 + 3]);
                    }
                }
            }
            __syncthreads();
        }
    }

    // x = F + b2 + H -> sA
#pragma unroll
    for (int q = 0; q < 2; q++)
#pragma unroll
        for (int u = 0; u < 4; u++) {
            int c = q * 64 + tx * 4 + u;
            float bb = b2[c];
#pragma unroll
            for (int r = 0; r < 4; r++) {
                int t = ty * 4 + r;
                sA[t * HH + c] = acc2[r][q * 4 + u] + bb + sH[t * HH + c];
            }
        }
    __syncthreads();

    // LayerNorm -> sH
    {
        int warp = tid >> 5, lane = tid & 31;
        for (int tt = warp * 8; tt < warp * 8 + 8; tt++) {
            float4 x = ((const float4*)sA)[tt * 32 + lane];
            float s1 = x.x + x.y + x.z + x.w;
            float s2 = fmaf(x.x, x.x, fmaf(x.y, x.y, fmaf(x.z, x.z, x.w * x.w)));
#pragma unroll
            for (int o = 16; o; o >>= 1) {
                s1 += __shfl_xor_sync(0xffffffffu, s1, o);
                s2 += __shfl_xor_sync(0xffffffffu, s2, o);
            }
            float mu  = s1 * (1.f / HH);
            float var = s2 * (1.f / HH) - mu * mu;
            float rs  = rsqrtf(var + 1e-5f);
            float4 gg = ((const float4*)lng)[lane];
            float4 bb = ((const float4*)lnb)[lane];
            float4 o;
            o.x = (x.x - mu) * rs * gg.x + bb.x;
            o.y = (x.y - mu) * rs * gg.y + bb.y;
            o.z = (x.z - mu) * rs * gg.z + bb.z;
            o.w = (x.w - mu) * rs * gg.w + bb.w;
            ((float4*)sH)[tt * 32 + lane] = o;
        }
    }
    __syncthreads();

    // ---- GEMM3: K = HN @ Wkp  (64x128x128)
    float acc3[4][8];
#pragma unroll
    for (int r = 0; r < 4; r++)
#pragma unroll
        for (int c = 0; c < 8; c++) acc3[r][c] = 0.f;

    {
        const float4* s = (const float4*)Wkp;   // row = 32 float4
#pragma unroll
        for (int j = 0; j < 4; j++) {
            int idx = tid + j * 256;
            cpasync16(swb + (unsigned)idx * 16,
                      s + (size_t)(idx >> 5) * 32 + (idx & 31));
        }
        cpcommit();
    }
    for (int kb = 0; kb < 4; kb++) {
        if (kb < 3) {
            const float4* s = (const float4*)Wkp;
            unsigned dst = swb + ((kb + 1) & 1) * 16384u;
#pragma unroll
            for (int j = 0; j < 4; j++) {
                int idx = tid + j * 256;
                cpasync16(dst + (unsigned)idx * 16,
                          s + (size_t)((kb + 1) * 32 + (idx >> 5)) * 32 + (idx & 31));
            }
            cpcommit();
            cpwait1();
        } else cpwait0();
        __syncthreads();
        const float* wb = sW + (kb & 1) * 4096;
#pragma unroll
        for (int kk = 0; kk < 32; kk++) {
            float hv[4];
#pragma unroll
            for (int r = 0; r < 4; r++) hv[r] = sH[(ty * 4 + r) * HH + kb * 32 + kk];
#pragma unroll
            for (int q = 0; q < 2; q++) {
                float4 w = ((const float4*)wb)[kk * 32 + q * 16 + tx];
#pragma unroll
                for (int r = 0; r < 4; r++) {
                    acc3[r][q * 4 + 0] = fmaf(hv[r], w.x, acc3[r][q * 4 + 0]);
                    acc3[r][q * 4 + 1] = fmaf(hv[r], w.y, acc3[r][q * 4 + 1]);
                    acc3[r][q * 4 + 2] = fmaf(hv[r], w.z, acc3[r][q * 4 + 2]);
                    acc3[r][q * 4 + 3] = fmaf(hv[r], w.w, acc3[r][q * 4 + 3]);
                }
            }
        }
        __syncthreads();
    }
    // write raw K into sA
#pragma unroll
    for (int q = 0; q < 2; q++)
#pragma unroll
        for (int u = 0; u < 4; u++) {
            int c = q * 64 + tx * 4 + u;
#pragma unroll
            for (int r = 0; r < 4; r++)
                sA[(ty * 4 + r) * HH + c] = acc3[r][q * 4 + u];
        }
    __syncthreads();

    // per-token norms
    {
        int warp = tid >> 5, lane = tid & 31;
        for (int tt = warp * 8; tt < warp * 8 + 8; tt++) {
            float4 x = ((const float4*)sA)[tt * 32 + lane];
            float ss = fmaf(x.x, x.x, fmaf(x.y, x.y, fmaf(x.z, x.z, x.w * x.w)));
#pragma unroll
            for (int o = 16; o; o >>= 1) ss += __shfl_xor_sync(0xffffffffu, ss, o);
            if (lane == 0) {
                float n = fmaxf(sqrtf(ss), 1e-12f);
                g_nrm[t0 + tt] = n;
                sInv[tt] = 1.f / n;
            }
        }
    }
    __syncthreads();

    // write normalized kn
    {
        float4* gk = (float4*)g_k;
        const float4* s = (const float4*)sA;
        for (int idx = tid; idx < TOK * 32; idx += 256) {
            float inv = sInv[idx >> 5];
            float4 v = s[idx];
            v.x *= inv; v.y *= inv; v.z *= inv; v.w *= inv;
            gk[(size_t)t0 * 32 + idx] = v;
        }
    }
}

// ---------------------------------------------------------------------------
// Kernel B: R6 scan + COHORT SYNC. One warp = one (batch,row); the 8 warps of
// a CTA read the same kn stream. A __syncthreads every 64 steps bounds warp
// drift to a 32KB window so the shared stream stays L1-resident (instead of
// every drifted warp paying an exposed L2 round-trip per step).
// Math/order identical to R6 -> bit-identical output.
// ---------------------------------------------------------------------------
__global__ void __launch_bounds__(256) kScan()
{
    const int warp = threadIdx.x >> 5, lane = threadIdx.x & 31;
    const int b = blockIdx.x >> 4;
    const int i = ((blockIdx.x & 15) << 3) + warp;

    const float*      kbase = g_k + (size_t)b * LL * HH;
    const ulonglong2* kp    = (const ulonglong2*)kbase + lane;
    const float*      np    = g_nrm + b * LL;
    const float*      kip   = kbase + i;

    ull m01 = 0ULL, m23 = 0ULL;

    ulonglong2 cur = __ldg(kp);
    float kni = __ldg(kip);
    float nrm = __ldg(np);

    int t = 0;
    for (int blk = 0; blk < LL / 64; blk++) {
        const int n = (blk == LL / 64 - 1) ? 63 : 64;   // last block ends at t=L-2
        for (int j = 0; j < n; j++, t++) {
            ulonglong2 nxt = __ldg(&kp[(size_t)(t + 1) * 32]);
            float kni_n = __ldg(&kip[(size_t)(t + 1) * HH]);
            float nrm_n = __ldg(&np[t + 1]);

            ull d = f2fma(m01, cur.x, 0ULL);
            d = f2fma(m23, cur.y, d);
            float lo, hi; upk2(d, lo, hi);
            float p = lo + hi;
            p += __shfl_xor_sync(0xffffffffu, p, 16);
            p += __shfl_xor_sync(0xffffffffu, p, 8);
            p += __shfl_xor_sync(0xffffffffu, p, 4);
            p += __shfl_xor_sync(0xffffffffu, p, 2);
            p += __shfl_xor_sync(0xffffffffu, p, 1);

            float c = fmaf(kni, nrm, -p);
            ull cd = pk2(c, c);
            m01 = f2fma(cd, cur.x, m01);
            m23 = f2fma(cd, cur.y, m23);

            cur = nxt; kni = kni_n; nrm = nrm_n;
        }
        __syncthreads();   // re-converge the 8-warp cohort (bounds L1 window)
    }

    // epilogue: q = kn[L-1] * nrm[L-1]  ->  read_i = nrm * (M . kn)
    ull d = f2fma(m01, cur.x, 0ULL);
    d = f2fma(m23, cur.y, d);
    float lo, hi; upk2(d, lo, hi);
    float p = lo + hi;
    p += __shfl_xor_sync(0xffffffffu, p, 16);
    p += __shfl_xor_sync(0xffffffffu, p, 8);
    p += __shfl_xor_sync(0xffffffffu, p, 4);
    p += __shfl_xor_sync(0xffffffffu, p, 2);
    p += __shfl_xor_sync(0xffffffffu, p, 1);
    if (lane == 0) g_read[b * HH + i] = p * nrm;
}

// ---------------------------------------------------------------------------
__global__ void __launch_bounds__(256) kC(const float* __restrict__ Wrp,
                                          const float* __restrict__ brp)
{
    int idx = blockIdx.x * 256 + threadIdx.x;
    if (idx >= BB * HH) return;
    int b = idx >> 7, d = idx & 127;
    float s = brp[d];
#pragma unroll 8
    for (int h = 0; h < HH; h++)
        s = fmaf(__ldg(&g_read[b * HH + h]), __ldg(&Wrp[h * HH + d]), s);
    g_r2[idx] = s;
}

// ---------------------------------------------------------------------------
__global__ void __launch_bounds__(256) kD(const float* __restrict__ Wout,
                                          const float* __restrict__ bout,
                                          float* __restrict__ out)
{
    __shared__ float sr[BB * HH];
    for (int idx = threadIdx.x; idx < BB * HH; idx += 256) sr[idx] = g_r2[idx];
    __syncthreads();
    int v = blockIdx.x * 256 + threadIdx.x;
    if (v >= VV) return;

    float acc[BB];
#pragma unroll
    for (int b = 0; b < BB; b++) acc[b] = 0.f;

#pragma unroll 1
    for (int h0 = 0; h0 < HH; h0 += 8) {
        float wv[8];
#pragma unroll
        for (int u = 0; u < 8; u++)
            wv[u] = __ldg(&Wout[(size_t)(h0 + u) * VV + v]);
#pragma unroll
        for (int u = 0; u < 8; u++)
#pragma unroll
            for (int b = 0; b < BB; b++)
                acc[b] = fmaf(sr[b * HH + h0 + u], wv[u], acc[b]);
    }
    float bo = __ldg(&bout[v]);
#pragma unroll
    for (int b = 0; b < BB; b++)
        out[(size_t)b * VV + v] = acc[b] + bo;
}

// ---------------------------------------------------------------------------
extern "C" void kernel_launch(void* const* d_in, const int* in_sizes, int n_in,
                              void* d_out, int out_size)
{
    const int*   seq   = (const int*)d_in[0];
    const float* embed = (const float*)d_in[1];
    const float* W1    = (const float*)d_in[2];
    const float* b1    = (const float*)d_in[3];
    const float* W2    = (const float*)d_in[4];
    const float* b2    = (const float*)d_in[5];
    const float* lng   = (const float*)d_in[6];
    const float* lnb   = (const float*)d_in[7];
    const float* Wkp   = (const float*)d_in[8];
    const float* Wrp   = (const float*)d_in[9];
    const float* brp   = (const float*)d_in[10];
    const float* Wout  = (const float*)d_in[11];
    const float* bout  = (const float*)d_in[12];
    float* out = (float*)d_out;

    cudaFuncSetAttribute(kA, cudaFuncAttributeMaxDynamicSharedMemorySize, 98304);

    kA<<<NTOK / TOK, 256, 98304>>>(seq, embed, W1, b1, W2, b2, lng, lnb, Wkp);
    kScan<<<(BB * HH) / 8, 256>>>();
    kC<<<(BB * HH + 255) / 256, 256>>>(Wrp, brp);
    kD<<<(VV + 255) / 256, 256>>>(Wout, bout, out);
}

// round 12
// speedup vs baseline: 1.0063x; 1.0063x over previous
#include <cuda_runtime.h>

typedef unsigned long long ull;

#define BB 32
#define LL 4096
#define HH 128
#define H2 256
#define VV 32000
#define TOK 64
#define NTOK (BB*LL)

// ---- helpers ---------------------------------------------------------------
__device__ __forceinline__ ull pk2(float lo, float hi) {
    ull r; asm("mov.b64 %0, {%1, %2};" : "=l"(r) : "f"(lo), "f"(hi)); return r;
}
__device__ __forceinline__ void upk2(ull v, float& lo, float& hi) {
    asm("mov.b64 {%0, %1}, %2;" : "=f"(lo), "=f"(hi) : "l"(v));
}
__device__ __forceinline__ ull f2fma(ull a, ull b, ull c) {
    ull d; asm("fma.rn.f32x2 %0, %1, %2, %3;" : "=l"(d) : "l"(a), "l"(b), "l"(c)); return d;
}
__device__ __forceinline__ void cpasync16(unsigned s, const void* g) {
    asm volatile("cp.async.ca.shared.global [%0], [%1], 16;" :: "r"(s), "l"(g));
}
__device__ __forceinline__ void cpcommit() { asm volatile("cp.async.commit_group;"); }
__device__ __forceinline__ void cpwait1()  { asm volatile("cp.async.wait_group 1;"); }
__device__ __forceinline__ void cpwait0()  { asm volatile("cp.async.wait_group 0;"); }

// Scratch
__device__ float g_k[(size_t)NTOK * HH];   // normalized kn, (B*L, H)
__device__ float g_nrm[NTOK];              // norm_eff
__device__ float g_read[BB * HH];
__device__ float g_r2[BB * HH];

// Dummy no-op: shifts the ncu capture window so the 4th launch is kScan.
__global__ void kNop() {}

// ---------------------------------------------------------------------------
// Kernel A (R10 verbatim): fused gather -> MLP(relu) -> residual+LN -> k-proj.
// 96KB smem, 2 CTAs/SM, cp.async double-buffered weight stages.
// ---------------------------------------------------------------------------
__global__ void __launch_bounds__(256, 2) kA(
    const int* __restrict__ seq, const float* __restrict__ embed,
    const float* __restrict__ W1, const float* __restrict__ b1,
    const float* __restrict__ W2, const float* __restrict__ b2,
    const float* __restrict__ lng, const float* __restrict__ lnb,
    const float* __restrict__ Wkp)
{
    extern __shared__ float sm[];
    float* sH = sm;              // 64 x 128 (32KB)
    float* sA = sm + 8192;       // 64 x 128 (32KB)
    float* sW = sm + 16384;      // 2 x 4096 (2 x 16KB stage buffers)
    __shared__ int sSeq[TOK];
    __shared__ float sInv[TOK];

    const int tid = threadIdx.x;
    const int t0  = blockIdx.x * TOK;
    if (tid < TOK) sSeq[tid] = seq[t0 + tid];
    __syncthreads();

    // gather embeddings
    {
        float4* d = (float4*)sH;
        const float4* e = (const float4*)embed;
        for (int idx = tid; idx < TOK * (HH / 4); idx += 256) {
            int r = idx >> 5;
            d[idx] = e[(size_t)sSeq[r] * (HH / 4) + (idx & 31)];
        }
    }
    __syncthreads();

    const int tx = tid & 15, ty = tid >> 4;
    const unsigned swb = (unsigned)__cvta_generic_to_shared(sW);

    float acc2[4][8];
#pragma unroll
    for (int r = 0; r < 4; r++)
#pragma unroll
        for (int c = 0; c < 8; c++) acc2[r][c] = 0.f;

    for (int hh = 0; hh < 2; hh++) {
        float acc[4][8];
#pragma unroll
        for (int r = 0; r < 4; r++)
#pragma unroll
            for (int c = 0; c < 8; c++) acc[r][c] = 0.f;

        {
            const float4* s = (const float4*)W1;
#pragma unroll
            for (int j = 0; j < 4; j++) {
                int idx = tid + j * 256;
                cpasync16(swb + (unsigned)idx * 16,
                          s + (size_t)(idx >> 5) * 64 + hh * 32 + (idx & 31));
            }
            cpcommit();
        }
        for (int kb = 0; kb < 4; kb++) {
            if (kb < 3) {
                const float4* s = (const float4*)W1;
                unsigned dst = swb + ((kb + 1) & 1) * 16384u;
#pragma unroll
                for (int j = 0; j < 4; j++) {
                    int idx = tid + j * 256;
                    cpasync16(dst + (unsigned)idx * 16,
                              s + (size_t)((kb + 1) * 32 + (idx >> 5)) * 64 + hh * 32 + (idx & 31));
                }
                cpcommit();
                cpwait1();
            } else cpwait0();
            __syncthreads();
            const float* wb = sW + (kb & 1) * 4096;
#pragma unroll
            for (int kk = 0; kk < 32; kk++) {
                float hv[4];
#pragma unroll
                for (int r = 0; r < 4; r++) hv[r] = sH[(ty * 4 + r) * HH + kb * 32 + kk];
#pragma unroll
                for (int q = 0; q < 2; q++) {
                    float4 w = ((const float4*)wb)[kk * 32 + q * 16 + tx];
#pragma unroll
                    for (int r = 0; r < 4; r++) {
                        acc[r][q * 4 + 0] = fmaf(hv[r], w.x, acc[r][q * 4 + 0]);
                        acc[r][q * 4 + 1] = fmaf(hv[r], w.y, acc[r][q * 4 + 1]);
                        acc[r][q * 4 + 2] = fmaf(hv[r], w.z, acc[r][q * 4 + 2]);
                        acc[r][q * 4 + 3] = fmaf(hv[r], w.w, acc[r][q * 4 + 3]);
                    }
                }
            }
            __syncthreads();
        }
#pragma unroll
        for (int q = 0; q < 2; q++)
#pragma unroll
            for (int u = 0; u < 4; u++) {
                int c = q * 64 + tx * 4 + u;
                float bb = b1[hh * 128 + c];
#pragma unroll
                for (int r = 0; r < 4; r++) {
                    float v = acc[r][q * 4 + u] + bb;
                    sA[(ty * 4 + r) * HH + c] = v > 0.f ? v : 0.f;
                }
            }
        __syncthreads();

        {
            const float4* s = (const float4*)W2;
#pragma unroll
            for (int j = 0; j < 4; j++) {
                int idx = tid + j * 256;
                cpasync16(swb + (unsigned)idx * 16,
                          s + (size_t)(hh * 128 + (idx >> 5)) * 32 + (idx & 31));
            }
            cpcommit();
        }
        for (int kb = 0; kb < 4; kb++) {
            if (kb < 3) {
                const float4* s = (const float4*)W2;
                unsigned dst = swb + ((kb + 1) & 1) * 16384u;
#pragma unroll
                for (int j = 0; j < 4; j++) {
                    int idx = tid + j * 256;
                    cpasync16(dst + (unsigned)idx * 16,
                              s + (size_t)(hh * 128 + (kb + 1) * 32 + (idx >> 5)) * 32 + (idx & 31));
                }
                cpcommit();
                cpwait1();
            } else cpwait0();
            __syncthreads();
            const float* wb = sW + (kb & 1) * 4096;
#pragma unroll
            for (int kk = 0; kk < 32; kk++) {
                float av[4];
#pragma unroll
                for (int r = 0; r < 4; r++) av[r] = sA[(ty * 4 + r) * HH + kb * 32 + kk];
#pragma unroll
                for (int q = 0; q < 2; q++) {
                    float4 w = ((const float4*)wb)[kk * 32 + q * 16 + tx];
#pragma unroll
                    for (int r = 0; r < 4; r++) {
                        acc2[r][q * 4 + 0] = fmaf(av[r], w.x, acc2[r][q * 4 + 0]);
                        acc2[r][q * 4 + 1] = fmaf(av[r], w.y, acc2[r][q * 4 + 1]);
                        acc2[r][q * 4 + 2] = fmaf(av[r], w.z, acc2[r][q * 4 + 2]);
                        acc2[r][q * 4 + 3] = fmaf(av[r], w.w, acc2[r][q * 4 + 3]);
                    }
                }
            }
            __syncthreads();
        }
    }

#pragma unroll
    for (int q = 0; q < 2; q++)
#pragma unroll
        for (int u = 0; u < 4; u++) {
            int c = q * 64 + tx * 4 + u;
            float bb = b2[c];
#pragma unroll
            for (int r = 0; r < 4; r++) {
                int t = ty * 4 + r;
                sA[t * HH + c] = acc2[r][q * 4 + u] + bb + sH[t * HH + c];
            }
        }
    __syncthreads();

    {
        int warp = tid >> 5, lane = tid & 31;
        for (int tt = warp * 8; tt < warp * 8 + 8; tt++) {
            float4 x = ((const float4*)sA)[tt * 32 + lane];
            float s1 = x.x + x.y + x.z + x.w;
            float s2 = fmaf(x.x, x.x, fmaf(x.y, x.y, fmaf(x.z, x.z, x.w * x.w)));
#pragma unroll
            for (int o = 16; o; o >>= 1) {
                s1 += __shfl_xor_sync(0xffffffffu, s1, o);
                s2 += __shfl_xor_sync(0xffffffffu, s2, o);
            }
            float mu  = s1 * (1.f / HH);
            float var = s2 * (1.f / HH) - mu * mu;
            float rs  = rsqrtf(var + 1e-5f);
            float4 gg = ((const float4*)lng)[lane];
            float4 bb = ((const float4*)lnb)[lane];
            float4 o;
            o.x = (x.x - mu) * rs * gg.x + bb.x;
            o.y = (x.y - mu) * rs * gg.y + bb.y;
            o.z = (x.z - mu) * rs * gg.z + bb.z;
            o.w = (x.w - mu) * rs * gg.w + bb.w;
            ((float4*)sH)[tt * 32 + lane] = o;
        }
    }
    __syncthreads();

    float acc3[4][8];
#pragma unroll
    for (int r = 0; r < 4; r++)
#pragma unroll
        for (int c = 0; c < 8; c++) acc3[r][c] = 0.f;

    {
        const float4* s = (const float4*)Wkp;
#pragma unroll
        for (int j = 0; j < 4; j++) {
            int idx = tid + j * 256;
            cpasync16(swb + (unsigned)idx * 16,
                      s + (size_t)(idx >> 5) * 32 + (idx & 31));
        }
        cpcommit();
    }
    for (int kb = 0; kb < 4; kb++) {
        if (kb < 3) {
            const float4* s = (const float4*)Wkp;
            unsigned dst = swb + ((kb + 1) & 1) * 16384u;
#pragma unroll
            for (int j = 0; j < 4; j++) {
                int idx = tid + j * 256;
                cpasync16(dst + (unsigned)idx * 16,
                          s + (size_t)((kb + 1) * 32 + (idx >> 5)) * 32 + (idx & 31));
            }
            cpcommit();
            cpwait1();
        } else cpwait0();
        __syncthreads();
        const float* wb = sW + (kb & 1) * 4096;
#pragma unroll
        for (int kk = 0; kk < 32; kk++) {
            float hv[4];
#pragma unroll
            for (int r = 0; r < 4; r++) hv[r] = sH[(ty * 4 + r) * HH + kb * 32 + kk];
#pragma unroll
            for (int q = 0; q < 2; q++) {
                float4 w = ((const float4*)wb)[kk * 32 + q * 16 + tx];
#pragma unroll
                for (int r = 0; r < 4; r++) {
                    acc3[r][q * 4 + 0] = fmaf(hv[r], w.x, acc3[r][q * 4 + 0]);
                    acc3[r][q * 4 + 1] = fmaf(hv[r], w.y, acc3[r][q * 4 + 1]);
                    acc3[r][q * 4 + 2] = fmaf(hv[r], w.z, acc3[r][q * 4 + 2]);
                    acc3[r][q * 4 + 3] = fmaf(hv[r], w.w, acc3[r][q * 4 + 3]);
                }
            }
        }
        __syncthreads();
    }
#pragma unroll
    for (int q = 0; q < 2; q++)
#pragma unroll
        for (int u = 0; u < 4; u++) {
            int c = q * 64 + tx * 4 + u;
#pragma unroll
            for (int r = 0; r < 4; r++)
                sA[(ty * 4 + r) * HH + c] = acc3[r][q * 4 + u];
        }
    __syncthreads();

    {
        int warp = tid >> 5, lane = tid & 31;
        for (int tt = warp * 8; tt < warp * 8 + 8; tt++) {
            float4 x = ((const float4*)sA)[tt * 32 + lane];
            float ss = fmaf(x.x, x.x, fmaf(x.y, x.y, fmaf(x.z, x.z, x.w * x.w)));
#pragma unroll
            for (int o = 16; o; o >>= 1) ss += __shfl_xor_sync(0xffffffffu, ss, o);
            if (lane == 0) {
                float n = fmaxf(sqrtf(ss), 1e-12f);
                g_nrm[t0 + tt] = n;
                sInv[tt] = 1.f / n;
            }
        }
    }
    __syncthreads();

    {
        float4* gk = (float4*)g_k;
        const float4* s = (const float4*)sA;
        for (int idx = tid; idx < TOK * 32; idx += 256) {
            float inv = sInv[idx >> 5];
            float4 v = s[idx];
            v.x *= inv; v.y *= inv; v.z *= inv; v.w *= inv;
            gk[(size_t)t0 * 32 + idx] = v;
        }
    }
}

// ---------------------------------------------------------------------------
// Kernel B v5: 4 rows/warp, 8-lane reduction groups (3 SHFLs in the chain
// instead of 5), prefetch depth 2 to cover L2 latency. 256 CTAs x 128 thr
// = 1024 warps; the 4 warps of a CTA share the kn stream (L1 reuse).
// Math: exact reassociation of the recurrence; c computed identically.
// ---------------------------------------------------------------------------
__global__ void __launch_bounds__(128) kScan()
{
    const int warpId = threadIdx.x >> 5, lane = threadIdx.x & 31;
    const int w  = blockIdx.x * 4 + warpId;   // 0..1023
    const int b  = w >> 5;                     // batch
    const int R0 = (w & 31) << 2;              // first of 4 rows
    const int g  = lane >> 3;                  // row group 0..3
    const int s  = lane & 7;                   // 8-lane segment

    const float*      kbase = g_k + (size_t)b * LL * HH;
    const ulonglong2* ks    = (const ulonglong2*)kbase + s * 4;  // +32 per t
    const float*      krow  = kbase + R0 + g;                    // +HH per t
    const float*      np    = g_nrm + b * LL;

    ull m0 = 0ULL, m1 = 0ULL, m2 = 0ULL, m3 = 0ULL,
        m4 = 0ULL, m5 = 0ULL, m6 = 0ULL, m7 = 0ULL;

    // pipeline: A = row t, B = row t+1
    ulonglong2 A0 = __ldg(ks + 0), A1 = __ldg(ks + 1),
               A2 = __ldg(ks + 2), A3 = __ldg(ks + 3);
    float kniA = __ldg(krow), nrmA = __ldg(np);
    ulonglong2 B0 = __ldg(ks + 32), B1 = __ldg(ks + 33),
               B2 = __ldg(ks + 34), B3 = __ldg(ks + 35);
    float kniB = __ldg(krow + HH), nrmB = __ldg(np + 1);

    for (int t = 0; t < LL - 1; t++) {
        // prefetch t+2 (clamped; redundant q-row load on final iters)
        int tn = t + 2 < LL - 1 ? t + 2 : LL - 1;
        const ulonglong2* kn2 = ks + (size_t)tn * 32;
        ulonglong2 C0 = __ldg(kn2 + 0), C1 = __ldg(kn2 + 1),
                   C2 = __ldg(kn2 + 2), C3 = __ldg(kn2 + 3);
        float kniC = __ldg(krow + (size_t)tn * HH);
        float nrmC = __ldg(np + tn);

        // dot over this lane's 16 elements (two 4-chains)
        ull u0 = f2fma(m0, A0.x, 0ULL); u0 = f2fma(m1, A0.y, u0);
        u0 = f2fma(m2, A1.x, u0);       u0 = f2fma(m3, A1.y, u0);
        ull u1 = f2fma(m4, A2.x, 0ULL); u1 = f2fma(m5, A2.y, u1);
        u1 = f2fma(m6, A3.x, u1);       u1 = f2fma(m7, A3.y, u1);
        float x0, x1, y0, y1; upk2(u0, x0, x1); upk2(u1, y0, y1);
        float p = (x0 + x1) + (y0 + y1);

        // 3-shuffle reduction within the 8-lane group
        p += __shfl_xor_sync(0xffffffffu, p, 4);
        p += __shfl_xor_sync(0xffffffffu, p, 2);
        p += __shfl_xor_sync(0xffffffffu, p, 1);

        float c = fmaf(kniA, nrmA, -p);     // raw k_row - (M.kn)_row
        ull cd = pk2(c, c);
        m0 = f2fma(cd, A0.x, m0); m1 = f2fma(cd, A0.y, m1);
        m2 = f2fma(cd, A1.x, m2); m3 = f2fma(cd, A1.y, m3);
        m4 = f2fma(cd, A2.x, m4); m5 = f2fma(cd, A2.y, m5);
        m6 = f2fma(cd, A3.x, m6); m7 = f2fma(cd, A3.y, m7);

        A0 = B0; A1 = B1; A2 = B2; A3 = B3; kniA = kniB; nrmA = nrmB;
        B0 = C0; B1 = C1; B2 = C2; B3 = C3; kniB = kniC; nrmB = nrmC;
    }

    // epilogue: A = row L-1 (q); read_row = nrm * (M . kn[L-1])
    ull u0 = f2fma(m0, A0.x, 0ULL); u0 = f2fma(m1, A0.y, u0);
    u0 = f2fma(m2, A1.x, u0);       u0 = f2fma(m3, A1.y, u0);
    ull u1 = f2fma(m4, A2.x, 0ULL); u1 = f2fma(m5, A2.y, u1);
    u1 = f2fma(m6, A3.x, u1);       u1 = f2fma(m7, A3.y, u1);
    float x0, x1, y0, y1; upk2(u0, x0, x1); upk2(u1, y0, y1);
    float p = (x0 + x1) + (y0 + y1);
    p += __shfl_xor_sync(0xffffffffu, p, 4);
    p += __shfl_xor_sync(0xffffffffu, p, 2);
    p += __shfl_xor_sync(0xffffffffu, p, 1);
    if (s == 0) g_read[b * HH + R0 + g] = p * nrmA;
}

// ---------------------------------------------------------------------------
__global__ void __launch_bounds__(256) kC(const float* __restrict__ Wrp,
                                          const float* __restrict__ brp)
{
    int idx = blockIdx.x * 256 + threadIdx.x;
    if (idx >= BB * HH) return;
    int b = idx >> 7, d = idx & 127;
    float s = brp[d];
#pragma unroll 8
    for (int h = 0; h < HH; h++)
        s = fmaf(__ldg(&g_read[b * HH + h]), __ldg(&Wrp[h * HH + d]), s);
    g_r2[idx] = s;
}

// ---------------------------------------------------------------------------
__global__ void __launch_bounds__(256) kD(const float* __restrict__ Wout,
                                          const float* __restrict__ bout,
                                          float* __restrict__ out)
{
    __shared__ float sr[BB * HH];
    for (int idx = threadIdx.x; idx < BB * HH; idx += 256) sr[idx] = g_r2[idx];
    __syncthreads();
    int v = blockIdx.x * 256 + threadIdx.x;
    if (v >= VV) return;

    float acc[BB];
#pragma unroll
    for (int b = 0; b < BB; b++) acc[b] = 0.f;

#pragma unroll 1
    for (int h0 = 0; h0 < HH; h0 += 8) {
        float wv[8];
#pragma unroll
        for (int u = 0; u < 8; u++)
            wv[u] = __ldg(&Wout[(size_t)(h0 + u) * VV + v]);
#pragma unroll
        for (int u = 0; u < 8; u++)
#pragma unroll
            for (int b = 0; b < BB; b++)
                acc[b] = fmaf(sr[b * HH + h0 + u], wv[u], acc[b]);
    }
    float bo = __ldg(&bout[v]);
#pragma unroll
    for (int b = 0; b < BB; b++)
        out[(size_t)b * VV + v] = acc[b] + bo;
}

// ---------------------------------------------------------------------------
extern "C" void kernel_launch(void* const* d_in, const int* in_sizes, int n_in,
                              void* d_out, int out_size)
{
    const int*   seq   = (const int*)d_in[0];
    const float* embed = (const float*)d_in[1];
    const float* W1    = (const float*)d_in[2];
    const float* b1    = (const float*)d_in[3];
    const float* W2    = (const float*)d_in[4];
    const float* b2    = (const float*)d_in[5];
    const float* lng   = (const float*)d_in[6];
    const float* lnb   = (const float*)d_in[7];
    const float* Wkp   = (const float*)d_in[8];
    const float* Wrp   = (const float*)d_in[9];
    const float* brp   = (const float*)d_in[10];
    const float* Wout  = (const float*)d_in[11];
    const float* bout  = (const float*)d_in[12];
    float* out = (float*)d_out;

    cudaFuncSetAttribute(kA, cudaFuncAttributeMaxDynamicSharedMemorySize, 98304);

    // Two no-op launches shift the ncu capture window (4th launch) onto kScan.
    kNop<<<1, 32>>>();
    kNop<<<1, 32>>>();
    kA<<<NTOK / TOK, 256, 98304>>>(seq, embed, W1, b1, W2, b2, lng, lnb, Wkp);
    kScan<<<256, 128>>>();
    kC<<<(BB * HH + 255) / 256, 256>>>(Wrp, brp);
    kD<<<(VV + 255) / 256, 256>>>(Wout, bout, out);
}

// round 13
// speedup vs baseline: 1.9349x; 1.9228x over previous
#include <cuda_runtime.h>

typedef unsigned long long ull;

#define BB 32
#define LL 4096
#define HH 128
#define H2 256
#define VV 32000
#define TOK 64
#define NTOK (BB*LL)
#define CH 32

// ---- helpers ---------------------------------------------------------------
__device__ __forceinline__ ull pk2(float lo, float hi) {
    ull r; asm("mov.b64 %0, {%1, %2};" : "=l"(r) : "f"(lo), "f"(hi)); return r;
}
__device__ __forceinline__ void upk2(ull v, float& lo, float& hi) {
    asm("mov.b64 {%0, %1}, %2;" : "=f"(lo), "=f"(hi) : "l"(v));
}
__device__ __forceinline__ ull f2fma(ull a, ull b, ull c) {
    ull d; asm("fma.rn.f32x2 %0, %1, %2, %3;" : "=l"(d) : "l"(a), "l"(b), "l"(c)); return d;
}
__device__ __forceinline__ void cpasync16(unsigned s, const void* g) {
    asm volatile("cp.async.ca.shared.global [%0], [%1], 16;" :: "r"(s), "l"(g));
}
__device__ __forceinline__ void cpcommit() { asm volatile("cp.async.commit_group;"); }
__device__ __forceinline__ void cpwait1()  { asm volatile("cp.async.wait_group 1;"); }
__device__ __forceinline__ void cpwait0()  { asm volatile("cp.async.wait_group 0;"); }

// Scratch
// g_k holds normalized kn with PERMUTED columns per token:
//   col c stored at pos(c) = ((c>>2)&3)*32 + (c>>4)*4 + (c&3)
// so kScan's 8-lane segment loads are contiguous 128B lines (conflict-free).
__device__ float g_k[(size_t)NTOK * HH];
__device__ float g_nrm[NTOK];
__device__ float g_read[BB * HH];
__device__ float g_r2[BB * HH];

// Dummy no-op: shifts the ncu capture window so it lands on kScan.
__global__ void kNop() {}

// ---------------------------------------------------------------------------
// Kernel A (R10 structure): fused gather -> MLP(relu) -> residual+LN -> k-proj
// 96KB smem, 2 CTAs/SM, cp.async double-buffered weight stages.
// Only change vs R10: final g_k write uses the permuted column layout.
// ---------------------------------------------------------------------------
__global__ void __launch_bounds__(256, 2) kA(
    const int* __restrict__ seq, const float* __restrict__ embed,
    const float* __restrict__ W1, const float* __restrict__ b1,
    const float* __restrict__ W2, const float* __restrict__ b2,
    const float* __restrict__ lng, const float* __restrict__ lnb,
    const float* __restrict__ Wkp)
{
    extern __shared__ float sm[];
    float* sH = sm;              // 64 x 128 (32KB)
    float* sA = sm + 8192;       // 64 x 128 (32KB)
    float* sW = sm + 16384;      // 2 x 4096 (2 x 16KB stage buffers)
    __shared__ int sSeq[TOK];
    __shared__ float sInv[TOK];

    const int tid = threadIdx.x;
    const int t0  = blockIdx.x * TOK;
    if (tid < TOK) sSeq[tid] = seq[t0 + tid];
    __syncthreads();

    {
        float4* d = (float4*)sH;
        const float4* e = (const float4*)embed;
        for (int idx = tid; idx < TOK * (HH / 4); idx += 256) {
            int r = idx >> 5;
            d[idx] = e[(size_t)sSeq[r] * (HH / 4) + (idx & 31)];
        }
    }
    __syncthreads();

    const int tx = tid & 15, ty = tid >> 4;
    const unsigned swb = (unsigned)__cvta_generic_to_shared(sW);

    float acc2[4][8];
#pragma unroll
    for (int r = 0; r < 4; r++)
#pragma unroll
        for (int c = 0; c < 8; c++) acc2[r][c] = 0.f;

    for (int hh = 0; hh < 2; hh++) {
        float acc[4][8];
#pragma unroll
        for (int r = 0; r < 4; r++)
#pragma unroll
            for (int c = 0; c < 8; c++) acc[r][c] = 0.f;

        {
            const float4* s = (const float4*)W1;
#pragma unroll
            for (int j = 0; j < 4; j++) {
                int idx = tid + j * 256;
                cpasync16(swb + (unsigned)idx * 16,
                          s + (size_t)(idx >> 5) * 64 + hh * 32 + (idx & 31));
            }
            cpcommit();
        }
        for (int kb = 0; kb < 4; kb++) {
            if (kb < 3) {
                const float4* s = (const float4*)W1;
                unsigned dst = swb + ((kb + 1) & 1) * 16384u;
#pragma unroll
                for (int j = 0; j < 4; j++) {
                    int idx = tid + j * 256;
                    cpasync16(dst + (unsigned)idx * 16,
                              s + (size_t)((kb + 1) * 32 + (idx >> 5)) * 64 + hh * 32 + (idx & 31));
                }
                cpcommit();
                cpwait1();
            } else cpwait0();
            __syncthreads();
            const float* wb = sW + (kb & 1) * 4096;
#pragma unroll
            for (int kk = 0; kk < 32; kk++) {
                float hv[4];
#pragma unroll
                for (int r = 0; r < 4; r++) hv[r] = sH[(ty * 4 + r) * HH + kb * 32 + kk];
#pragma unroll
                for (int q = 0; q < 2; q++) {
                    float4 w = ((const float4*)wb)[kk * 32 + q * 16 + tx];
#pragma unroll
                    for (int r = 0; r < 4; r++) {
                        acc[r][q * 4 + 0] = fmaf(hv[r], w.x, acc[r][q * 4 + 0]);
                        acc[r][q * 4 + 1] = fmaf(hv[r], w.y, acc[r][q * 4 + 1]);
                        acc[r][q * 4 + 2] = fmaf(hv[r], w.z, acc[r][q * 4 + 2]);
                        acc[r][q * 4 + 3] = fmaf(hv[r], w.w, acc[r][q * 4 + 3]);
                    }
                }
            }
            __syncthreads();
        }
#pragma unroll
        for (int q = 0; q < 2; q++)
#pragma unroll
            for (int u = 0; u < 4; u++) {
                int c = q * 64 + tx * 4 + u;
                float bb = b1[hh * 128 + c];
#pragma unroll
                for (int r = 0; r < 4; r++) {
                    float v = acc[r][q * 4 + u] + bb;
                    sA[(ty * 4 + r) * HH + c] = v > 0.f ? v : 0.f;
                }
            }
        __syncthreads();

        {
            const float4* s = (const float4*)W2;
#pragma unroll
            for (int j = 0; j < 4; j++) {
                int idx = tid + j * 256;
                cpasync16(swb + (unsigned)idx * 16,
                          s + (size_t)(hh * 128 + (idx >> 5)) * 32 + (idx & 31));
            }
            cpcommit();
        }
        for (int kb = 0; kb < 4; kb++) {
            if (kb < 3) {
                const float4* s = (const float4*)W2;
                unsigned dst = swb + ((kb + 1) & 1) * 16384u;
#pragma unroll
                for (int j = 0; j < 4; j++) {
                    int idx = tid + j * 256;
                    cpasync16(dst + (unsigned)idx * 16,
                              s + (size_t)(hh * 128 + (kb + 1) * 32 + (idx >> 5)) * 32 + (idx & 31));
                }
                cpcommit();
                cpwait1();
            } else cpwait0();
            __syncthreads();
            const float* wb = sW + (kb & 1) * 4096;
#pragma unroll
            for (int kk = 0; kk < 32; kk++) {
                float av[4];
#pragma unroll
                for (int r = 0; r < 4; r++) av[r] = sA[(ty * 4 + r) * HH + kb * 32 + kk];
#pragma unroll
                for (int q = 0; q < 2; q++) {
                    float4 w = ((const float4*)wb)[kk * 32 + q * 16 + tx];
#pragma unroll
                    for (int r = 0; r < 4; r++) {
                        acc2[r][q * 4 + 0] = fmaf(av[r], w.x, acc2[r][q * 4 + 0]);
                        acc2[r][q * 4 + 1] = fmaf(av[r], w.y, acc2[r][q * 4 + 1]);
                        acc2[r][q * 4 + 2] = fmaf(av[r], w.z, acc2[r][q * 4 + 2]);
                        acc2[r][q * 4 + 3] = fmaf(av[r], w.w, acc2[r][q * 4 + 3]);
                    }
                }
            }
            __syncthreads();
        }
    }

#pragma unroll
    for (int q = 0; q < 2; q++)
#pragma unroll
        for (int u = 0; u < 4; u++) {
            int c = q * 64 + tx * 4 + u;
            float bb = b2[c];
#pragma unroll
            for (int r = 0; r < 4; r++) {
                int t = ty * 4 + r;
                sA[t * HH + c] = acc2[r][q * 4 + u] + bb + sH[t * HH + c];
            }
        }
    __syncthreads();

    {
        int warp = tid >> 5, lane = tid & 31;
        for (int tt = warp * 8; tt < warp * 8 + 8; tt++) {
            float4 x = ((const float4*)sA)[tt * 32 + lane];
            float s1 = x.x + x.y + x.z + x.w;
            float s2 = fmaf(x.x, x.x, fmaf(x.y, x.y, fmaf(x.z, x.z, x.w * x.w)));
#pragma unroll
            for (int o = 16; o; o >>= 1) {
                s1 += __shfl_xor_sync(0xffffffffu, s1, o);
                s2 += __shfl_xor_sync(0xffffffffu, s2, o);
            }
            float mu  = s1 * (1.f / HH);
            float var = s2 * (1.f / HH) - mu * mu;
            float rs  = rsqrtf(var + 1e-5f);
            float4 gg = ((const float4*)lng)[lane];
            float4 bb = ((const float4*)lnb)[lane];
            float4 o;
            o.x = (x.x - mu) * rs * gg.x + bb.x;
            o.y = (x.y - mu) * rs * gg.y + bb.y;
            o.z = (x.z - mu) * rs * gg.z + bb.z;
            o.w = (x.w - mu) * rs * gg.w + bb.w;
            ((float4*)sH)[tt * 32 + lane] = o;
        }
    }
    __syncthreads();

    float acc3[4][8];
#pragma unroll
    for (int r = 0; r < 4; r++)
#pragma unroll
        for (int c = 0; c < 8; c++) acc3[r][c] = 0.f;

    {
        const float4* s = (const float4*)Wkp;
#pragma unroll
        for (int j = 0; j < 4; j++) {
            int idx = tid + j * 256;
            cpasync16(swb + (unsigned)idx * 16,
                      s + (size_t)(idx >> 5) * 32 + (idx & 31));
        }
        cpcommit();
    }
    for (int kb = 0; kb < 4; kb++) {
        if (kb < 3) {
            const float4* s = (const float4*)Wkp;
            unsigned dst = swb + ((kb + 1) & 1) * 16384u;
#pragma unroll
            for (int j = 0; j < 4; j++) {
                int idx = tid + j * 256;
                cpasync16(dst + (unsigned)idx * 16,
                          s + (size_t)((kb + 1) * 32 + (idx >> 5)) * 32 + (idx & 31));
            }
            cpcommit();
            cpwait1();
        } else cpwait0();
        __syncthreads();
        const float* wb = sW + (kb & 1) * 4096;
#pragma unroll
        for (int kk = 0; kk < 32; kk++) {
            float hv[4];
#pragma unroll
            for (int r = 0; r < 4; r++) hv[r] = sH[(ty * 4 + r) * HH + kb * 32 + kk];
#pragma unroll
            for (int q = 0; q < 2; q++) {
                float4 w = ((const float4*)wb)[kk * 32 + q * 16 + tx];
#pragma unroll
                for (int r = 0; r < 4; r++) {
                    acc3[r][q * 4 + 0] = fmaf(hv[r], w.x, acc3[r][q * 4 + 0]);
                    acc3[r][q * 4 + 1] = fmaf(hv[r], w.y, acc3[r][q * 4 + 1]);
                    acc3[r][q * 4 + 2] = fmaf(hv[r], w.z, acc3[r][q * 4 + 2]);
                    acc3[r][q * 4 + 3] = fmaf(hv[r], w.w, acc3[r][q * 4 + 3]);
                }
            }
        }
        __syncthreads();
    }
#pragma unroll
    for (int q = 0; q < 2; q++)
#pragma unroll
        for (int u = 0; u < 4; u++) {
            int c = q * 64 + tx * 4 + u;
#pragma unroll
            for (int r = 0; r < 4; r++)
                sA[(ty * 4 + r) * HH + c] = acc3[r][q * 4 + u];
        }
    __syncthreads();

    {
        int warp = tid >> 5, lane = tid & 31;
        for (int tt = warp * 8; tt < warp * 8 + 8; tt++) {
            float4 x = ((const float4*)sA)[tt * 32 + lane];
            float ss = fmaf(x.x, x.x, fmaf(x.y, x.y, fmaf(x.z, x.z, x.w * x.w)));
#pragma unroll
            for (int o = 16; o; o >>= 1) ss += __shfl_xor_sync(0xffffffffu, ss, o);
            if (lane == 0) {
                float n = fmaxf(sqrtf(ss), 1e-12f);
                g_nrm[t0 + tt] = n;
                sInv[tt] = 1.f / n;
            }
        }
    }
    __syncthreads();

    // write normalized kn with PERMUTED columns:
    //   source float4 idx c4 (cols c4*4..c4*4+3) -> dest float4 (c4&3)*8 + (c4>>2)
    {
        float4* gk = (float4*)g_k;
        const float4* sp = (const float4*)sA;
        for (int idx = tid; idx < TOK * 32; idx += 256) {
            int tt = idx >> 5, c4 = idx & 31;
            float inv = sInv[tt];
            float4 v = sp[idx];
            v.x *= inv; v.y *= inv; v.z *= inv; v.w *= inv;
            int dst4 = (c4 & 3) * 8 + (c4 >> 2);
            gk[(size_t)(t0 + tt) * 32 + dst4] = v;
        }
    }
}

// ---------------------------------------------------------------------------
// Kernel B v6: smem-staged, conflict-free scan.
// 128 CTAs x 256 thr; CTA owns 32 rows of one batch (4 CTAs/batch).
// Warp = 4 rows (g = lane>>3) x 8 segments (s = lane&7); lane holds 16
// M-elements (cols s*16..s*16+15, stored at permuted float4s j*8+s).
// kn chunks (32 steps, 16KB) double-buffered via cp.async; each LDS.128 is
// one contiguous 128B line broadcast to 4 lane-groups (1 wavefront).
// ---------------------------------------------------------------------------
__global__ void __launch_bounds__(256) kScan()
{
    __shared__ __align__(16) float sKn[2][CH * HH];
    __shared__ float sNr[2][CH];

    const int tid = threadIdx.x;
    const int b  = blockIdx.x >> 2;
    const int qq = blockIdx.x & 3;
    const int w = tid >> 5, lane = tid & 31;
    const int g = lane >> 3, s = lane & 7;
    const int row = qq * 32 + w * 4 + g;
    // permuted float offset of original column 'row'
    const int roff = ((row >> 2) & 3) * 32 + (row >> 4) * 4 + (row & 3);

    const float* kb = g_k + (size_t)b * LL * HH;
    const float* nb = g_nrm + b * LL;

    // stage chunk 0
    {
        unsigned dk = (unsigned)__cvta_generic_to_shared(&sKn[0][0]);
#pragma unroll
        for (int j = 0; j < 4; j++)
            cpasync16(dk + (unsigned)(tid + j * 256) * 16, kb + (tid + j * 256) * 4);
        if (tid < 8) {
            unsigned dn = (unsigned)__cvta_generic_to_shared(&sNr[0][0]);
            cpasync16(dn + (unsigned)tid * 16, nb + tid * 4);
        }
        cpcommit();
        cpwait0();
    }
    __syncthreads();

    ull m[8];
#pragma unroll
    for (int j = 0; j < 8; j++) m[j] = 0ULL;

    for (int c = 0; c < LL / CH; c++) {
        const int cur = c & 1;
        if (c < LL / CH - 1) {
            unsigned dk = (unsigned)__cvta_generic_to_shared(&sKn[cur ^ 1][0]);
            const float* src = kb + (size_t)(c + 1) * CH * HH;
#pragma unroll
            for (int j = 0; j < 4; j++)
                cpasync16(dk + (unsigned)(tid + j * 256) * 16, src + (tid + j * 256) * 4);
            if (tid < 8) {
                unsigned dn = (unsigned)__cvta_generic_to_shared(&sNr[cur ^ 1][0]);
                cpasync16(dn + (unsigned)tid * 16, nb + (c + 1) * CH + tid * 4);
            }
            cpcommit();
        }

        const float* kc = &sKn[cur][0];
        const float* nc = &sNr[cur][0];
        const int nsteps = (c == LL / CH - 1) ? CH - 1 : CH;   // last chunk: t=L-1 is q

        for (int tl = 0; tl < nsteps; tl++) {
            const float* base = kc + tl * HH;
            const ulonglong2* kl = (const ulonglong2*)base;
            // conflict-free: float4 index j*8+s -> bytes j*128 + s*16 (contiguous line)
            ulonglong2 a0 = kl[0 * 8 + s];
            ulonglong2 a1 = kl[1 * 8 + s];
            ulonglong2 a2 = kl[2 * 8 + s];
            ulonglong2 a3 = kl[3 * 8 + s];
            float kr = base[roff];
            float nr = nc[tl];

            ull u0 = f2fma(m[0], a0.x, 0ULL); u0 = f2fma(m[1], a0.y, u0);
            u0 = f2fma(m[2], a1.x, u0);       u0 = f2fma(m[3], a1.y, u0);
            ull u1 = f2fma(m[4], a2.x, 0ULL); u1 = f2fma(m[5], a2.y, u1);
            u1 = f2fma(m[6], a3.x, u1);       u1 = f2fma(m[7], a3.y, u1);
            float x0, x1, y0, y1; upk2(u0, x0, x1); upk2(u1, y0, y1);
            float p = (x0 + x1) + (y0 + y1);
            p += __shfl_xor_sync(0xffffffffu, p, 4);
            p += __shfl_xor_sync(0xffffffffu, p, 2);
            p += __shfl_xor_sync(0xffffffffu, p, 1);

            float cc = fmaf(kr, nr, -p);       // raw k_row - (M.kn)_row
            ull cd = pk2(cc, cc);
            m[0] = f2fma(cd, a0.x, m[0]); m[1] = f2fma(cd, a0.y, m[1]);
            m[2] = f2fma(cd, a1.x, m[2]); m[3] = f2fma(cd, a1.y, m[3]);
            m[4] = f2fma(cd, a2.x, m[4]); m[5] = f2fma(cd, a2.y, m[5]);
            m[6] = f2fma(cd, a3.x, m[6]); m[7] = f2fma(cd, a3.y, m[7]);
        }

        if (c < LL / CH - 1) cpwait0();
        __syncthreads();
    }

    // epilogue: q = kn[L-1] (chunk 127 lives in buffer 1, local step CH-1)
    {
        const float* base = &sKn[1][0] + (CH - 1) * HH;
        const ulonglong2* kl = (const ulonglong2*)base;
        ulonglong2 a0 = kl[0 * 8 + s];
        ulonglong2 a1 = kl[1 * 8 + s];
        ulonglong2 a2 = kl[2 * 8 + s];
        ulonglong2 a3 = kl[3 * 8 + s];
        float nr = sNr[1][CH - 1];

        ull u0 = f2fma(m[0], a0.x, 0ULL); u0 = f2fma(m[1], a0.y, u0);
        u0 = f2fma(m[2], a1.x, u0);       u0 = f2fma(m[3], a1.y, u0);
        ull u1 = f2fma(m[4], a2.x, 0ULL); u1 = f2fma(m[5], a2.y, u1);
        u1 = f2fma(m[6], a3.x, u1);       u1 = f2fma(m[7], a3.y, u1);
        float x0, x1, y0, y1; upk2(u0, x0, x1); upk2(u1, y0, y1);
        float p = (x0 + x1) + (y0 + y1);
        p += __shfl_xor_sync(0xffffffffu, p, 4);
        p += __shfl_xor_sync(0xffffffffu, p, 2);
        p += __shfl_xor_sync(0xffffffffu, p, 1);
        if (s == 0) g_read[b * HH + row] = p * nr;
    }
}

// ---------------------------------------------------------------------------
__global__ void __launch_bounds__(256) kC(const float* __restrict__ Wrp,
                                          const float* __restrict__ brp)
{
    int idx = blockIdx.x * 256 + threadIdx.x;
    if (idx >= BB * HH) return;
    int b = idx >> 7, d = idx & 127;
    float s = brp[d];
#pragma unroll 8
    for (int h = 0; h < HH; h++)
        s = fmaf(__ldg(&g_read[b * HH + h]), __ldg(&Wrp[h * HH + d]), s);
    g_r2[idx] = s;
}

// ---------------------------------------------------------------------------
__global__ void __launch_bounds__(256) kD(const float* __restrict__ Wout,
                                          const float* __restrict__ bout,
                                          float* __restrict__ out)
{
    __shared__ float sr[BB * HH];
    for (int idx = threadIdx.x; idx < BB * HH; idx += 256) sr[idx] = g_r2[idx];
    __syncthreads();
    int v = blockIdx.x * 256 + threadIdx.x;
    if (v >= VV) return;

    float acc[BB];
#pragma unroll
    for (int b = 0; b < BB; b++) acc[b] = 0.f;

#pragma unroll 1
    for (int h0 = 0; h0 < HH; h0 += 8) {
        float wv[8];
#pragma unroll
        for (int u = 0; u < 8; u++)
            wv[u] = __ldg(&Wout[(size_t)(h0 + u) * VV + v]);
#pragma unroll
        for (int u = 0; u < 8; u++)
#pragma unroll
            for (int b = 0; b < BB; b++)
                acc[b] = fmaf(sr[b * HH + h0 + u], wv[u], acc[b]);
    }
    float bo = __ldg(&bout[v]);
#pragma unroll
    for (int b = 0; b < BB; b++)
        out[(size_t)b * VV + v] = acc[b] + bo;
}

// ---------------------------------------------------------------------------
extern "C" void kernel_launch(void* const* d_in, const int* in_sizes, int n_in,
                              void* d_out, int out_size)
{
    const int*   seq   = (const int*)d_in[0];
    const float* embed = (const float*)d_in[1];
    const float* W1    = (const float*)d_in[2];
    const float* b1    = (const float*)d_in[3];
    const float* W2    = (const float*)d_in[4];
    const float* b2    = (const float*)d_in[5];
    const float* lng   = (const float*)d_in[6];
    const float* lnb   = (const float*)d_in[7];
    const float* Wkp   = (const float*)d_in[8];
    const float* Wrp   = (const float*)d_in[9];
    const float* brp   = (const float*)d_in[10];
    const float* Wout  = (const float*)d_in[11];
    const float* bout  = (const float*)d_in[12];
    float* out = (float*)d_out;

    cudaFuncSetAttribute(kA, cudaFuncAttributeMaxDynamicSharedMemorySize, 98304);

    // Two no-op launches keep the ncu capture window on kScan.
    kNop<<<1, 32>>>();
    kNop<<<1, 32>>>();
    kA<<<NTOK / TOK, 256, 98304>>>(seq, embed, W1, b1, W2, b2, lng, lnb, Wkp);
    kScan<<<BB * 4, 256>>>();
    kC<<<(BB * HH + 255) / 256, 256>>>(Wrp, brp);
    kD<<<(VV + 255) / 256, 256>>>(Wout, bout, out);
}